// round 1
// baseline (speedup 1.0000x reference)
#include <cuda_runtime.h>
#include <cstdint>

// ---------------------------------------------------------------------------
// RNN_MultiRegional_SAC: 512-step recurrence h = relu(0.9 h + 0.1 (h @ W^T + drive))
// W_rec [3072,3072] has only 5 nonzero 1024x1024 blocks:
//   rows 0..1023   (str):  W00 = -str2str_fixed        (cols 0..1023)
//                          W02 = mask(c<717)*clip(m12str) (cols 2048..3071)
//   rows 1024..2047(thal): W10 = clip(str2thal)*diag(c<512?+1:-1) (cols 0..1023)
//   rows 2048..3071(m1):   W21 = clip(thal2m1)          (cols 1024..2047)
//                          W22 = clip(m12m1)*diag(c<717?+1:-1)    (cols 2048..3071)
// clip = hardtanh(1e-10, 1)
// Output buffer layout (float32): [mean 32*512][std 32*512][hn_last 32*3072][rnn_out 32*512*3072]
// ---------------------------------------------------------------------------

#define Hh   1024
#define H3   3072
#define Bz   32
#define Tz   512
#define NINH 307
#define NEXC 717
#define HH   (Hh*Hh)

// packed W blocks: [W00, W02, W10, W21, W22], each 1024x1024 row-major (row=output n, col=k)
__device__ float g_W[5u * HH];
// ping-pong hidden state, layout [n][b] (b contiguous)
__device__ float g_h[2][H3 * Bz];

// ---------------- f32x2 helpers ----------------
__device__ __forceinline__ unsigned long long pack2(float x, float y) {
    unsigned long long r;
    asm("mov.b64 %0, {%1, %2};" : "=l"(r) : "f"(x), "f"(y));
    return r;
}
__device__ __forceinline__ void fma2(unsigned long long& acc, unsigned long long a, unsigned long long b) {
    asm("fma.rn.f32x2 %0, %1, %2, %0;" : "+l"(acc) : "l"(a), "l"(b));
}
__device__ __forceinline__ void unpack2(unsigned long long v, float& x, float& y) {
    asm("mov.b64 {%0, %1}, %2;" : "=f"(x), "=f"(y) : "l"(v));
}

// ---------------- prep: build packed W blocks (runs once per graph replay) ----
__global__ void prep_kernel(const float* __restrict__ w_str2thal,
                            const float* __restrict__ w_m12m1,
                            const float* __restrict__ w_m12str,
                            const float* __restrict__ w_thal2m1,
                            const float* __restrict__ fixedw) {
    int idx = blockIdx.x * blockDim.x + threadIdx.x;
    if (idx >= HH) return;
    int c = idx & (Hh - 1);
    // W00 = -fixed (no clip on the fixed matrix)
    g_W[0 * HH + idx] = -fixedw[idx];
    // W02 = mask(c<NEXC) * clip(m12str)
    float v = fminf(fmaxf(w_m12str[idx], 1e-10f), 1.0f);
    g_W[1 * HH + idx] = (c < NEXC) ? v : 0.0f;
    // W10 = clip(str2thal) * (c<512 ? +1 : -1)
    v = fminf(fmaxf(w_str2thal[idx], 1e-10f), 1.0f);
    g_W[2 * HH + idx] = (c < (Hh / 2)) ? v : -v;
    // W21 = clip(thal2m1)
    g_W[3 * HH + idx] = fminf(fmaxf(w_thal2m1[idx], 1e-10f), 1.0f);
    // W22 = clip(m12m1) * (c<NEXC ? +1 : -1)
    v = fminf(fmaxf(w_m12m1[idx], 1e-10f), 1.0f);
    g_W[4 * HH + idx] = (c < NEXC) ? v : -v;
}

// ---------------- init: load h0 from hn input, transpose to [n][b] ------------
__global__ void init_kernel(const float* __restrict__ hn) {
    int idx = blockIdx.x * blockDim.x + threadIdx.x;
    if (idx >= H3 * Bz) return;
    int n = idx >> 5, b = idx & 31;
    g_h[0][idx] = hn[b * H3 + n];
}

// ---------------- per-step kernel --------------------------------------------
// Block: 16 output n, all 32 b, full K reduction over its region's segments.
// 256 threads = 16 (4 n-groups x 4 b-groups) positions x 16 K-split.
// Thread tile: 4 n x 8 b (4 f32x2 accumulators per n).
__global__ void __launch_bounds__(256) step_kernel(int t,
                                                   const float* __restrict__ inp,
                                                   const float* __restrict__ inp_weight,
                                                   float* __restrict__ rnn) {
    __shared__ float sH[64 * 36];           // [k][b] padded row 36 (bank-clean f32x2/128 loads)
    __shared__ float sW[64 * 20];           // [k][n] padded row 20 (16B-aligned float4 loads)
    __shared__ float sRed[256 * 33];        // reduction scratch, padded row 33

    const float* __restrict__ hprev = g_h[t & 1];
    float* __restrict__ hnext = g_h[(t + 1) & 1];

    const int tx = threadIdx.x;
    const int bid = blockIdx.x;

    // Block -> (region, n0). Heavy regions first (better wave balance on 148 SMs).
    int region, n0;
    if (bid < 64)       { region = 0; n0 = bid * 16; }
    else if (bid < 128) { region = 2; n0 = 2048 + (bid - 64) * 16; }
    else                { region = 1; n0 = 1024 + (bid - 128) * 16; }
    const int rowbase = n0 & (Hh - 1);

    int nseg;
    const float* segW[2];
    int segHoff[2];
    if (region == 0)      { nseg = 2; segW[0] = g_W;          segHoff[0] = 0;
                                       segW[1] = g_W + 1 * HH; segHoff[1] = 2048; }
    else if (region == 1) { nseg = 1; segW[0] = g_W + 2 * HH; segHoff[0] = 0; }
    else                  { nseg = 2; segW[0] = g_W + 3 * HH; segHoff[0] = 1024;
                                       segW[1] = g_W + 4 * HH; segHoff[1] = 2048; }

    const int ks  = tx >> 4;          // 0..15  K-split lane
    const int pos = tx & 15;
    const int ng  = pos & 3;          // n-group (4 n each)
    const int bg  = pos >> 2;         // b-group (8 b each)

    unsigned long long acc[16];
#pragma unroll
    for (int i = 0; i < 16; i++) acc[i] = 0ull;

    const int total_tiles = nseg << 4;   // 16 tiles of K=64 per segment

    // prefetch tile 0 into registers
    float rH[8], rW[4];
    {
        const float* Hp = hprev + segHoff[0] * Bz;
        const float* Wp = segW[0] + (size_t)rowbase * Hh;
#pragma unroll
        for (int i = 0; i < 8; i++) rH[i] = Hp[tx + i * 256];
#pragma unroll
        for (int j = 0; j < 4; j++) {
            int idx = tx + j * 256;
            rW[j] = Wp[(idx >> 6) * Hh + (idx & 63)];
        }
    }

    for (int tile = 0; tile < total_tiles; tile++) {
        // store staged tile to smem
#pragma unroll
        for (int i = 0; i < 8; i++) {
            int idx = tx + i * 256;                       // k*32 + b
            sH[(idx >> 5) * 36 + (idx & 31)] = rH[i];
        }
#pragma unroll
        for (int j = 0; j < 4; j++) {
            int idx = tx + j * 256;                       // n*64 + k
            sW[(idx & 63) * 20 + (idx >> 6)] = rW[j];
        }
        __syncthreads();

        // prefetch next tile
        if (tile + 1 < total_tiles) {
            int seg = (tile + 1) >> 4;
            int kb  = ((tile + 1) & 15) << 6;
            const float* Hn = hprev + (segHoff[seg] + kb) * Bz;
            const float* Wn = segW[seg] + (size_t)rowbase * Hh + kb;
#pragma unroll
            for (int i = 0; i < 8; i++) rH[i] = Hn[tx + i * 256];
#pragma unroll
            for (int j = 0; j < 4; j++) {
                int idx = tx + j * 256;
                rW[j] = Wn[(idx >> 6) * Hh + (idx & 63)];
            }
        }

        // compute: 4 k per thread, 4n x 8b register tile, packed f32x2 FMAs
#pragma unroll
        for (int kk = 0; kk < 4; kk++) {
            int k = (ks << 2) + kk;
            float4 wv = *(const float4*)&sW[k * 20 + (ng << 2)];
            ulonglong2 ha = *(const ulonglong2*)&sH[k * 36 + (bg << 3)];
            ulonglong2 hb = *(const ulonglong2*)&sH[k * 36 + (bg << 3) + 4];
            unsigned long long w;
            w = pack2(wv.x, wv.x);
            fma2(acc[0], w, ha.x); fma2(acc[1], w, ha.y); fma2(acc[2], w, hb.x); fma2(acc[3], w, hb.y);
            w = pack2(wv.y, wv.y);
            fma2(acc[4], w, ha.x); fma2(acc[5], w, ha.y); fma2(acc[6], w, hb.x); fma2(acc[7], w, hb.y);
            w = pack2(wv.z, wv.z);
            fma2(acc[8], w, ha.x); fma2(acc[9], w, ha.y); fma2(acc[10], w, hb.x); fma2(acc[11], w, hb.y);
            w = pack2(wv.w, wv.w);
            fma2(acc[12], w, ha.x); fma2(acc[13], w, ha.y); fma2(acc[14], w, hb.x); fma2(acc[15], w, hb.y);
        }
        __syncthreads();
    }

    // ---- cross-K-split reduction (16 partials per position) ----
#pragma unroll
    for (int i = 0; i < 16; i++) {
        float x, y;
        unpack2(acc[i], x, y);
        sRed[tx * 33 + 2 * i]     = x;
        sRed[tx * 33 + 2 * i + 1] = y;
    }
    __syncthreads();
#pragma unroll
    for (int s = 128; s >= 16; s >>= 1) {
        if (tx < s) {
#pragma unroll
            for (int i = 0; i < 32; i++)
                sRed[tx * 33 + i] += sRed[(tx + s) * 33 + i];
        }
        __syncthreads();
    }

    // ---- epilogue: relu update + write hnext (transposed) and rnn_out ----
    // 512 outputs (16n x 32b), 2 per thread (same n, adjacent b)
    {
        int idx = tx * 2;                 // n_l*32 + b
        int n_l = idx >> 5;
        int b   = idx & 31;               // even
        int n   = n0 + n_l;
        int ngp = n_l >> 2, ni = n_l & 3;
        int bgp = b >> 3,   p  = (b & 7) >> 1;
        int ppos = bgp * 4 + ngp;
        float mm0 = sRed[ppos * 33 + (ni * 4 + p) * 2 + 0];
        float mm1 = sRed[ppos * 33 + (ni * 4 + p) * 2 + 1];

        float iw0 = inp_weight[0 * H3 + n];
        float iw1 = inp_weight[1 * H3 + n];
        float iw2 = inp_weight[2 * H3 + n];
        float iw3 = inp_weight[3 * H3 + n];

        // b (even)
        {
            float4 iv = ((const float4*)inp)[b * Tz + t];
            float d = iv.x * iw0 + iv.y * iw1 + iv.z * iw2 + iv.w * iw3;
            float hp = hprev[n * Bz + b];
            float v = fmaxf(0.9f * hp + 0.1f * (mm0 + d), 0.0f);
            hnext[n * Bz + b] = v;
            rnn[((size_t)(b * Tz + t)) * H3 + n] = v;
        }
        // b+1 (odd)
        {
            int b1 = b + 1;
            float4 iv = ((const float4*)inp)[b1 * Tz + t];
            float d = iv.x * iw0 + iv.y * iw1 + iv.z * iw2 + iv.w * iw3;
            float hp = hprev[n * Bz + b1];
            float v = fmaxf(0.9f * hp + 0.1f * (mm1 + d), 0.0f);
            hnext[n * Bz + b1] = v;
            rnn[((size_t)(b1 * Tz + t)) * H3 + n] = v;
        }
    }
}

// ---------------- heads: mean/std over masked (m1) region ---------------------
__global__ void head_kernel(const float* __restrict__ rnn,
                            const float* __restrict__ mean_w, const float* __restrict__ mean_b,
                            const float* __restrict__ std_w,  const float* __restrict__ std_b,
                            float* __restrict__ mean_out, float* __restrict__ std_out) {
    int warp = blockIdx.x * 8 + (threadIdx.x >> 5);   // = b*512 + t, grid sized exactly
    int lane = threadIdx.x & 31;
    const float* row = rnn + (size_t)warp * H3 + 2048;
    float sm = 0.0f, ss = 0.0f;
#pragma unroll 8
    for (int i = lane; i < Hh; i += 32) {
        float v = row[i];
        sm += v * mean_w[2048 + i];
        ss += v * std_w[2048 + i];
    }
#pragma unroll
    for (int off = 16; off; off >>= 1) {
        sm += __shfl_down_sync(0xFFFFFFFFu, sm, off);
        ss += __shfl_down_sync(0xFFFFFFFFu, ss, off);
    }
    if (lane == 0) {
        mean_out[warp] = sm + mean_b[0];
        float s = ss + std_b[0];
        std_out[warp] = fminf(fmaxf(s, -5.0f), 10.0f);
    }
}

// ---------------- hn_last copy ------------------------------------------------
__global__ void hn_kernel(const float* __restrict__ rnn, float* __restrict__ hn_out) {
    int idx = blockIdx.x * blockDim.x + threadIdx.x;
    if (idx >= Bz * H3) return;
    int b = idx / H3, n = idx - b * H3;
    hn_out[idx] = rnn[((size_t)(b * Tz + (Tz - 1))) * H3 + n];
}

// ---------------- launch -------------------------------------------------------
extern "C" void kernel_launch(void* const* d_in, const int* in_sizes, int n_in,
                              void* d_out, int out_size) {
    const float* inp        = (const float*)d_in[0];   // [32,512,4]
    const float* hn         = (const float*)d_in[1];   // [1,32,3072]
    // d_in[2] = w_str2str (unused: its mask is all-zeros in the reference)
    const float* w_str2thal = (const float*)d_in[3];
    const float* w_m12m1    = (const float*)d_in[4];
    const float* w_m12str   = (const float*)d_in[5];
    const float* w_thal2m1  = (const float*)d_in[6];
    const float* fixedw     = (const float*)d_in[7];
    const float* inp_weight = (const float*)d_in[8];   // [4,3072]
    const float* mean_w     = (const float*)d_in[9];   // [1,3072]
    const float* mean_b     = (const float*)d_in[10];  // [1]
    const float* std_w      = (const float*)d_in[11];
    const float* std_b      = (const float*)d_in[12];
    // d_in[13] = sampling flag (always the vectorized path)

    float* out      = (float*)d_out;
    float* mean_out = out;                         // 32*512
    float* std_out  = out + 16384;                 // 32*512
    float* hn_out   = out + 32768;                 // 32*3072
    float* rnn      = out + 131072;                // 32*512*3072

    prep_kernel<<<(HH + 255) / 256, 256>>>(w_str2thal, w_m12m1, w_m12str, w_thal2m1, fixedw);
    init_kernel<<<(H3 * Bz + 255) / 256, 256>>>(hn);

    for (int t = 0; t < Tz; t++)
        step_kernel<<<192, 256>>>(t, inp, inp_weight, rnn);

    head_kernel<<<2048, 256>>>(rnn, mean_w, mean_b, std_w, std_b, mean_out, std_out);
    hn_kernel<<<(Bz * H3 + 255) / 256, 256>>>(rnn, hn_out);
}

// round 2
// speedup vs baseline: 1.2459x; 1.2459x over previous
#include <cuda_runtime.h>
#include <cstdint>

// ---------------------------------------------------------------------------
// RNN_MultiRegional_SAC: 512-step recurrence h = relu(0.9 h + 0.1 (h @ W^T + drive))
// Packed W blocks (each 1024x1024): [W00=-fixed, W02, W10, W21, W22]
// rows 0..1023:    W00 (h[0:1024])  + W02 (h[2048:3072])
// rows 1024..2047: W10 (h[0:1024])
// rows 2048..3071: W21 (h[1024:2048]) + W22 (h[2048:3072])
// Output layout (float32): [mean 32*512][std 32*512][hn_last 32*3072][rnn_out 32*512*3072]
// ---------------------------------------------------------------------------

#define Hh   1024
#define H3   3072
#define Bz   32
#define Tz   512
#define NEXC 717
#define HH   (Hh*Hh)

__device__ __align__(128) float g_W[5u * HH];
__device__ __align__(128) float g_h[2][H3 * Bz];   // [n][b]

// ---------------- f32x2 helpers ----------------
__device__ __forceinline__ unsigned long long pack2(float x, float y) {
    unsigned long long r;
    asm("mov.b64 %0, {%1, %2};" : "=l"(r) : "f"(x), "f"(y));
    return r;
}
__device__ __forceinline__ void fma2(unsigned long long& acc, unsigned long long a, unsigned long long b) {
    asm("fma.rn.f32x2 %0, %1, %2, %0;" : "+l"(acc) : "l"(a), "l"(b));
}
__device__ __forceinline__ void unpack2(unsigned long long v, float& x, float& y) {
    asm("mov.b64 {%0, %1}, %2;" : "=f"(x), "=f"(y) : "l"(v));
}
__device__ __forceinline__ void cp16(void* dst, const void* src) {
    unsigned d = (unsigned)__cvta_generic_to_shared(dst);
    asm volatile("cp.async.cg.shared.global [%0], [%1], 16;" :: "r"(d), "l"(src));
}
#define CP_COMMIT() asm volatile("cp.async.commit_group;")
#define CP_WAIT0()  asm volatile("cp.async.wait_group 0;")

// ---------------- prep: build packed W blocks ---------------------------------
__global__ void prep_kernel(const float* __restrict__ w_str2thal,
                            const float* __restrict__ w_m12m1,
                            const float* __restrict__ w_m12str,
                            const float* __restrict__ w_thal2m1,
                            const float* __restrict__ fixedw) {
    int idx = blockIdx.x * blockDim.x + threadIdx.x;
    if (idx >= HH) return;
    int c = idx & (Hh - 1);
    g_W[0 * HH + idx] = -fixedw[idx];
    float v = fminf(fmaxf(w_m12str[idx], 1e-10f), 1.0f);
    g_W[1 * HH + idx] = (c < NEXC) ? v : 0.0f;
    v = fminf(fmaxf(w_str2thal[idx], 1e-10f), 1.0f);
    g_W[2 * HH + idx] = (c < (Hh / 2)) ? v : -v;
    g_W[3 * HH + idx] = fminf(fmaxf(w_thal2m1[idx], 1e-10f), 1.0f);
    v = fminf(fmaxf(w_m12m1[idx], 1e-10f), 1.0f);
    g_W[4 * HH + idx] = (c < NEXC) ? v : -v;
}

// ---------------- init: hn -> g_h[0] transposed to [n][b] ---------------------
__global__ void init_kernel(const float* __restrict__ hn) {
    int idx = blockIdx.x * blockDim.x + threadIdx.x;
    if (idx >= H3 * Bz) return;
    int n = idx >> 5, b = idx & 31;
    g_h[0][idx] = hn[b * H3 + n];
}

// ---------------- per-step kernel ---------------------------------------------
// Grid 384: bids [0,128) region0 (8 rows, K=2048), [128,256) region2 (8 rows,
// K=2048), [256,384) region1 (8 rows, K=1024).
// Block 256 threads = 8 K-split warps x 32 positions (4 n-pairs x 8 b-quads).
// Thread tile: 2n x 4b (4 f32x2 accumulators). K-tile 64, cp.async double-buffered.
__global__ void __launch_bounds__(256) step_kernel(int t,
                                                   const float* __restrict__ inp,
                                                   const float* __restrict__ inp_weight,
                                                   float* __restrict__ rnn) {
    __shared__ __align__(16) float sW[2][8 * 68];     // [n][k], pad 68
    __shared__ __align__(16) float sH[2][64 * 36];    // [k][b], pad 36
    __shared__ float sRed[256 * 9];                   // 8 partial pairs per thread

    const float* __restrict__ hprev = g_h[t & 1];
    float* __restrict__ hnext = g_h[(t + 1) & 1];

    const int tx  = threadIdx.x;
    const int bid = blockIdx.x;

    int region, n0;
    if (bid < 128)      { region = 0; n0 = bid * 8; }
    else if (bid < 256) { region = 2; n0 = 2048 + (bid - 128) * 8; }
    else                { region = 1; n0 = 1024 + (bid - 256) * 8; }
    const int rowbase = n0 & (Hh - 1);

    int nseg;
    const float* segW[2];
    int segHoff[2];
    if (region == 0)      { nseg = 2; segW[0] = g_W;          segHoff[0] = 0;
                                       segW[1] = g_W + 1 * HH; segHoff[1] = 2048; }
    else if (region == 1) { nseg = 1; segW[0] = g_W + 2 * HH; segHoff[0] = 0;
                                       segW[1] = g_W + 2 * HH; segHoff[1] = 0; }
    else                  { nseg = 2; segW[0] = g_W + 3 * HH; segHoff[0] = 1024;
                                       segW[1] = g_W + 4 * HH; segHoff[1] = 2048; }

    const int ks  = tx >> 5;          // warp id = K-split lane (0..7)
    const int pos = tx & 31;
    const int ng  = pos & 3;          // n-pair index (n_l = ng*2 + {0,1})
    const int bg  = pos >> 2;         // b-quad index (b = bg*4 + 0..3)

    unsigned long long acc[4];        // [nl][q] : nl*2+q
#pragma unroll
    for (int i = 0; i < 4; i++) acc[i] = 0ull;

    const int total_tiles = nseg << 4;

    // ---- stage tile 0 ----
    {
        const float* Wp = segW[0] + (size_t)rowbase * Hh;
        if (tx < 128) {
            int r = tx >> 4, c = tx & 15;
            cp16(&sW[0][r * 68 + c * 4], Wp + r * Hh + c * 4);
        }
        const float* Hp = hprev + segHoff[0] * Bz;
#pragma unroll
        for (int i = 0; i < 2; i++) {
            int chunk = tx + i * 256;                 // 16B chunk id
            cp16(&sH[0][(chunk >> 3) * 36 + (chunk & 7) * 4], Hp + chunk * 4);
        }
        CP_COMMIT();
    }

    int buf = 0;
    for (int tile = 0; tile < total_tiles; tile++) {
        CP_WAIT0();
        __syncthreads();

        // stage next tile into other buffer (overlapped with compute)
        if (tile + 1 < total_tiles) {
            int seg = (tile + 1) >> 4;
            int kb  = ((tile + 1) & 15) << 6;
            const float* Wp = segW[seg] + (size_t)rowbase * Hh + kb;
            if (tx < 128) {
                int r = tx >> 4, c = tx & 15;
                cp16(&sW[buf ^ 1][r * 68 + c * 4], Wp + r * Hh + c * 4);
            }
            const float* Hp = hprev + (segHoff[seg] + kb) * Bz;
#pragma unroll
            for (int i = 0; i < 2; i++) {
                int chunk = tx + i * 256;
                cp16(&sH[buf ^ 1][(chunk >> 3) * 36 + (chunk & 7) * 4], Hp + chunk * 4);
            }
            CP_COMMIT();
        }

        // compute this tile: 8 k per thread
#pragma unroll
        for (int kk = 0; kk < 8; kk++) {
            int k = (ks << 3) + kk;
            float w0 = sW[buf][(ng * 2) * 68 + k];
            float w1 = sW[buf][(ng * 2 + 1) * 68 + k];
            ulonglong2 hv = *(const ulonglong2*)&sH[buf][k * 36 + bg * 4];
            unsigned long long W0 = pack2(w0, w0);
            unsigned long long W1 = pack2(w1, w1);
            fma2(acc[0], W0, hv.x);
            fma2(acc[1], W0, hv.y);
            fma2(acc[2], W1, hv.x);
            fma2(acc[3], W1, hv.y);
        }
        buf ^= 1;
    }

    // ---- write partials ----
#pragma unroll
    for (int j = 0; j < 4; j++) {
        float x, y;
        unpack2(acc[j], x, y);
        sRed[tx * 9 + j * 2]     = x;
        sRed[tx * 9 + j * 2 + 1] = y;
    }
    __syncthreads();

    // ---- combine + epilogue: thread tx handles output (n_l = tx>>5, b = tx&31)
    {
        int n_l = tx >> 5;
        int b   = tx & 31;
        int n   = n0 + n_l;
        int ngo = n_l >> 1, nl = n_l & 1;
        int bgo = b >> 2,   q  = (b >> 1) & 1, par = b & 1;
        int poso = bgo * 4 + ngo;
        int slot = (nl * 2 + q) * 2 + par;

        float s = 0.0f;
#pragma unroll
        for (int kso = 0; kso < 8; kso++)
            s += sRed[(kso * 32 + poso) * 9 + slot];

        float iw0 = inp_weight[0 * H3 + n];
        float iw1 = inp_weight[1 * H3 + n];
        float iw2 = inp_weight[2 * H3 + n];
        float iw3 = inp_weight[3 * H3 + n];
        float4 iv = ((const float4*)inp)[b * Tz + t];
        float d = iv.x * iw0 + iv.y * iw1 + iv.z * iw2 + iv.w * iw3;

        float hp = hprev[n * Bz + b];
        float v = fmaxf(0.9f * hp + 0.1f * (s + d), 0.0f);
        hnext[n * Bz + b] = v;
        rnn[((size_t)(b * Tz + t)) * H3 + n] = v;
    }
}

// ---------------- heads: mean/std over masked (m1) region ---------------------
__global__ void head_kernel(const float* __restrict__ rnn,
                            const float* __restrict__ mean_w, const float* __restrict__ mean_b,
                            const float* __restrict__ std_w,  const float* __restrict__ std_b,
                            float* __restrict__ mean_out, float* __restrict__ std_out) {
    int warp = blockIdx.x * 8 + (threadIdx.x >> 5);   // = b*512 + t
    int lane = threadIdx.x & 31;
    const float* row = rnn + (size_t)warp * H3 + 2048;
    float sm = 0.0f, ss = 0.0f;
#pragma unroll 8
    for (int i = lane; i < Hh; i += 32) {
        float v = row[i];
        sm += v * mean_w[2048 + i];
        ss += v * std_w[2048 + i];
    }
#pragma unroll
    for (int off = 16; off; off >>= 1) {
        sm += __shfl_down_sync(0xFFFFFFFFu, sm, off);
        ss += __shfl_down_sync(0xFFFFFFFFu, ss, off);
    }
    if (lane == 0) {
        mean_out[warp] = sm + mean_b[0];
        float s = ss + std_b[0];
        std_out[warp] = fminf(fmaxf(s, -5.0f), 10.0f);
    }
}

// ---------------- hn_last copy -------------------------------------------------
__global__ void hn_kernel(const float* __restrict__ rnn, float* __restrict__ hn_out) {
    int idx = blockIdx.x * blockDim.x + threadIdx.x;
    if (idx >= Bz * H3) return;
    int b = idx / H3, n = idx - b * H3;
    hn_out[idx] = rnn[((size_t)(b * Tz + (Tz - 1))) * H3 + n];
}

// ---------------- launch --------------------------------------------------------
extern "C" void kernel_launch(void* const* d_in, const int* in_sizes, int n_in,
                              void* d_out, int out_size) {
    const float* inp        = (const float*)d_in[0];   // [32,512,4]
    const float* hn         = (const float*)d_in[1];   // [1,32,3072]
    // d_in[2] = w_str2str (unused: its mask is all-zeros in the reference)
    const float* w_str2thal = (const float*)d_in[3];
    const float* w_m12m1    = (const float*)d_in[4];
    const float* w_m12str   = (const float*)d_in[5];
    const float* w_thal2m1  = (const float*)d_in[6];
    const float* fixedw     = (const float*)d_in[7];
    const float* inp_weight = (const float*)d_in[8];   // [4,3072]
    const float* mean_w     = (const float*)d_in[9];   // [1,3072]
    const float* mean_b     = (const float*)d_in[10];  // [1]
    const float* std_w      = (const float*)d_in[11];
    const float* std_b      = (const float*)d_in[12];
    // d_in[13] = sampling flag

    float* out      = (float*)d_out;
    float* mean_out = out;                         // 32*512
    float* std_out  = out + 16384;                 // 32*512
    float* hn_out   = out + 32768;                 // 32*3072
    float* rnn      = out + 131072;                // 32*512*3072

    prep_kernel<<<(HH + 255) / 256, 256>>>(w_str2thal, w_m12m1, w_m12str, w_thal2m1, fixedw);
    init_kernel<<<(H3 * Bz + 255) / 256, 256>>>(hn);

    for (int t = 0; t < Tz; t++)
        step_kernel<<<384, 256>>>(t, inp, inp_weight, rnn);

    head_kernel<<<2048, 256>>>(rnn, mean_w, mean_b, std_w, std_b, mean_out, std_out);
    hn_kernel<<<(Bz * H3 + 255) / 256, 256>>>(rnn, hn_out);
}